// round 10
// baseline (speedup 1.0000x reference)
#include <cuda_runtime.h>
#include <math.h>
#include <stdint.h>

#define BB 256     // batch
#define TT 512     // time steps
#define DIN 128    // input dim
#define HH 256     // hidden
#define G4 1024    // 4*H
#define OUTF 128   // final out features
#define BHH (BB * HH)

#define NB_CTAS 128
#define NGROUPS 8        // batch-tile groups (32 rows each)
#define GROUP_CTAS 16
#define WPAD 260
#define RPAD 68

// SMEM layout (floats)
#define OFF_WS0 0
#define OFF_WS1 (64 * WPAD)
#define OFF_HS0 (128 * WPAD)
#define OFF_HS1 (160 * WPAD)
#define OFF_RS0 (192 * WPAD)
#define OFF_RS1 (OFF_RS0 + 32 * RPAD)
#define FUSED_FLOATS (OFF_RS1 + 32 * RPAD)   // 54,272 floats = 217,088 B

typedef unsigned long long ull;

// ---------------- scratch (device globals; no allocations allowed) ----------
__device__ float g_XP[(size_t)TT * BB * G4];    // layer-0 x_proj [T,B,4H]
__device__ float g_H0[2 * BHH];                 // layer-0 h ping-pong
__device__ float g_H1[2 * BHH];                 // layer-1 h ping-pong
__device__ float g_HLAST[BHH];                  // final h1
__device__ unsigned g_flag[NGROUPS * GROUP_CTAS * 32];  // per-CTA flags, 128B apart

// ---------------- helpers ----------------------------------------------------
__device__ __forceinline__ void ffma2(ull& d, ull a, ull b) {
    asm("fma.rn.f32x2 %0, %1, %2, %0;" : "+l"(d) : "l"(a), "l"(b));
}
__device__ __forceinline__ float red2(ull v) {
    float lo = __uint_as_float((unsigned)(v & 0xffffffffu));
    float hi = __uint_as_float((unsigned)(v >> 32));
    return lo + hi;
}
__device__ __forceinline__ float fsig(float x) {
    return __fdividef(1.f, 1.f + __expf(-x));
}
__device__ __forceinline__ float ftanh(float x) {
    return 2.f * __fdividef(1.f, 1.f + __expf(-2.f * x)) - 1.f;
}

// ---------------- init: zero h buffers and flags ------------------------------
__global__ void init_kernel() {
    int i = blockIdx.x * blockDim.x + threadIdx.x;
    if (i < 2 * BHH) { g_H0[i] = 0.f; g_H1[i] = 0.f; }
    if (i < NGROUPS * GROUP_CTAS * 32) g_flag[i] = 0u;
}

// ---------------- generic GEMM + bias (f32x2) -- validated ---------------------
template <int K>
__global__ void gemm_bias_kernel(const float* __restrict__ A,
                                 size_t rowStrideB, size_t strideT,
                                 const float* __restrict__ W,
                                 const float* __restrict__ b1,
                                 const float* __restrict__ b2,
                                 float* __restrict__ outp, int ldOut)
{
    __shared__ __align__(16) float As[64][68];
    __shared__ __align__(16) float Ws[64][68];

    const int t   = blockIdx.z;
    const int bb  = blockIdx.y * 64;
    const int nn  = blockIdx.x * 64;
    const int tid = threadIdx.x;
    const int r0  = tid & 15;
    const int c0  = tid >> 4;

    ull acc2[4][4];
#pragma unroll
    for (int m = 0; m < 4; m++)
#pragma unroll
        for (int n = 0; n < 4; n++) acc2[m][n] = 0ull;

    const float* Abase = A + (size_t)bb * rowStrideB + (size_t)t * strideT;
    const float* Wbase = W + (size_t)nn * K;

    for (int kt = 0; kt < K; kt += 64) {
#pragma unroll
        for (int i = 0; i < 4; i++) {
            int lin = i * 256 + tid;
            int row = lin >> 4;
            int c4  = (lin & 15) * 4;
            *(float4*)&As[row][c4] =
                *(const float4*)(Abase + (size_t)row * rowStrideB + kt + c4);
            *(float4*)&Ws[row][c4] =
                *(const float4*)(Wbase + (size_t)row * K + kt + c4);
        }
        __syncthreads();

#pragma unroll
        for (int k = 0; k < 64; k += 4) {
            ulonglong2 a2[4], w2[4];
#pragma unroll
            for (int m = 0; m < 4; m++) a2[m] = *(ulonglong2*)&As[r0 + 16 * m][k];
#pragma unroll
            for (int n = 0; n < 4; n++) w2[n] = *(ulonglong2*)&Ws[c0 + 16 * n][k];
#pragma unroll
            for (int m = 0; m < 4; m++)
#pragma unroll
                for (int n = 0; n < 4; n++) {
                    ffma2(acc2[m][n], a2[m].x, w2[n].x);
                    ffma2(acc2[m][n], a2[m].y, w2[n].y);
                }
        }
        __syncthreads();
    }

#pragma unroll
    for (int m = 0; m < 4; m++)
#pragma unroll
        for (int n = 0; n < 4; n++) {
            int row = bb + r0 + 16 * m;
            int col = nn + c0 + 16 * n;
            float bias = (b1 != nullptr) ? (b1[col] + b2[col]) : 0.f;
            outp[((size_t)t * BB + row) * ldOut + col] = red2(acc2[m][n]) + bias;
        }
}

// ---------------- fused 2-layer persistent LSTM --------------------------------
// 128 CTAs x 256 threads. CTA (jt,bt): hidden slice jj..jj+15, batch bb..bb+31,
// for BOTH layers. Iteration u (0..TT): layer0 computes h0(u) (skip u==TT);
// layer1 computes h1(u-1) = f(h1(u-2), h0(u-1)), reading W_ih1 from L2 via
// register-pipelined LDG (no cp.async, no named barriers). K-split across
// 2 warpgroups; partials via two SMEM buffers (Rs0/Rs1).
__global__ void __launch_bounds__(256, 1)
lstm_fused_kernel(const float* __restrict__ xp,     // [T,B,4H] layer-0 x_proj
                  const float* __restrict__ Whh0,   // [4H,H]
                  const float* __restrict__ Whh1,   // [4H,H]
                  const float* __restrict__ Wih1,   // [4H,H]
                  const float* __restrict__ bih1,
                  const float* __restrict__ bhh1,
                  float* __restrict__ h0buf,        // [2][B,H]
                  float* __restrict__ h1buf,        // [2][B,H]
                  float* __restrict__ hlast)        // [B,H]
{
    extern __shared__ __align__(16) float smg[];
    float* Ws0 = smg + OFF_WS0;   // [64][WPAD]
    float* Ws1 = smg + OFF_WS1;   // [64][WPAD]
    float* Hs0 = smg + OFF_HS0;   // [32][WPAD]
    float* Hs1 = smg + OFF_HS1;   // [32][WPAD]
    float* Rs0 = smg + OFF_RS0;   // [32][RPAD]
    float* Rs1 = smg + OFF_RS1;   // [32][RPAD]

    const int tid = threadIdx.x;
    const int jt  = blockIdx.x & 15;
    const int bt  = blockIdx.x >> 4;
    const int jj  = jt * 16;
    const int bb  = bt * 32;
    const int kg  = tid >> 7;        // warpgroup: k half
    const int lt  = tid & 127;
    const int jl  = lt >> 3;         // 0..15 hidden unit within tile
    const int br  = lt & 7;          // batch rows br,br+8,br+16,br+24
    const int j   = jj + jl;
    const int kb  = kg * 128;        // k base for this warpgroup
    // W_ih1 row base for this thread's 4 gate rows (row g*HH + j)
    const float* wih_t = Wih1 + (size_t)j * HH + kb;

    // ---- load both W_hh slices: smem row = g*16 + jloc
#pragma unroll
    for (int i = 0; i < 16; i++) {
        int lin  = i * 256 + tid;       // 0..4095 float4 units
        int srow = lin >> 6;            // 0..63
        int c4   = (lin & 63) * 4;
        int g    = srow >> 4;
        int jloc = srow & 15;
        size_t grow = (size_t)(g * HH + jj + jloc) * HH + c4;
        *(float4*)&Ws0[srow * WPAD + c4] = *(const float4*)(Whh0 + grow);
        *(float4*)&Ws1[srow * WPAD + c4] = *(const float4*)(Whh1 + grow);
    }

    float cacc0[4] = {0.f, 0.f, 0.f, 0.f};
    float cacc1[4] = {0.f, 0.f, 0.f, 0.f};
    float bias1[4];
    float xv_cur[4][4], xv_nxt[4][4];
    if (kg == 0) {
#pragma unroll
        for (int g = 0; g < 4; g++)
            bias1[g] = bih1[g * HH + j] + bhh1[g * HH + j];
#pragma unroll
        for (int m = 0; m < 4; m++) {
            const float* xr = xp + (size_t)(bb + br + 8 * m) * G4;
#pragma unroll
            for (int g = 0; g < 4; g++) xv_cur[m][g] = __ldg(xr + g * HH + j);
        }
    }
    __syncthreads();   // W slices ready

    for (int u = 0; u <= TT; u++) {
        // ---- wait for all group CTAs to have finished iteration u-1
        if (u > 0) {
            if (tid < GROUP_CTAS) {
                volatile unsigned* f = &g_flag[(bt * GROUP_CTAS + tid) * 32];
                while (*f < (unsigned)u) {}
                __threadfence();
            }
            __syncthreads();
        }

        // ---- stage h0(u-1) and h1(u-2) tiles into SMEM
        const float* hin0 = h0buf + (size_t)((u + 1) & 1) * BHH;
        const float* hin1 = h1buf + (size_t)(u & 1) * BHH;
#pragma unroll
        for (int i = 0; i < 8; i++) {
            int lin = i * 256 + tid;    // 0..2047 float4 units
            int row = lin >> 6;         // 0..31
            int c4  = (lin & 63) * 4;
            size_t goff = (size_t)(bb + row) * HH + c4;
            *(float4*)&Hs0[row * WPAD + c4] = __ldcg((const float4*)(hin0 + goff));
            *(float4*)&Hs1[row * WPAD + c4] = __ldcg((const float4*)(hin1 + goff));
        }
        __syncthreads();

        // ---- prefetch next iteration's x_proj (layer 0)
        if (kg == 0 && u + 1 < TT) {
            const float* xpt = xp + (size_t)(u + 1) * BB * G4;
#pragma unroll
            for (int m = 0; m < 4; m++) {
                const float* xr = xpt + (size_t)(bb + br + 8 * m) * G4;
#pragma unroll
                for (int g = 0; g < 4; g++) xv_nxt[m][g] = __ldg(xr + g * HH + j);
            }
        }

        // ================= layer 0 GEMM: h0(u-1) . W_hh0 =================
        if (u < TT) {
            ull acc0[4][4];
#pragma unroll
            for (int m = 0; m < 4; m++)
#pragma unroll
                for (int g = 0; g < 4; g++) acc0[m][g] = 0ull;

#pragma unroll 4
            for (int k = kb; k < kb + 128; k += 4) {
                ulonglong2 h2[4], w2[4];
#pragma unroll
                for (int m = 0; m < 4; m++)
                    h2[m] = *(ulonglong2*)&Hs0[(br + 8 * m) * WPAD + k];
#pragma unroll
                for (int g = 0; g < 4; g++)
                    w2[g] = *(ulonglong2*)&Ws0[(g * 16 + jl) * WPAD + k];
#pragma unroll
                for (int m = 0; m < 4; m++)
#pragma unroll
                    for (int g = 0; g < 4; g++) {
                        ffma2(acc0[m][g], h2[m].x, w2[g].x);
                        ffma2(acc0[m][g], h2[m].y, w2[g].y);
                    }
            }

            // kg1 publishes layer-0 partials into Rs0
            if (kg == 1) {
#pragma unroll
                for (int m = 0; m < 4; m++)
#pragma unroll
                    for (int g = 0; g < 4; g++)
                        Rs0[(8 * m + br) * RPAD + g * 16 + jl] = red2(acc0[m][g]);
                __syncthreads();
            } else {
                __syncthreads();
                // kg0: epilogue layer 0 -> h0(u)
                float* hout = h0buf + (size_t)(u & 1) * BHH;
#pragma unroll
                for (int m = 0; m < 4; m++) {
                    int b = bb + br + 8 * m;
                    const float* rrow = &Rs0[(8 * m + br) * RPAD];
                    float vi = red2(acc0[m][0]) + rrow[0 * 16 + jl] + xv_cur[m][0];
                    float vf = red2(acc0[m][1]) + rrow[1 * 16 + jl] + xv_cur[m][1];
                    float vg = red2(acc0[m][2]) + rrow[2 * 16 + jl] + xv_cur[m][2];
                    float vo = red2(acc0[m][3]) + rrow[3 * 16 + jl] + xv_cur[m][3];

                    float ig = fsig(vi), fg = fsig(vf), gg = ftanh(vg), og = fsig(vo);
                    float cn = fg * cacc0[m] + ig * gg;
                    cacc0[m] = cn;
                    __stcg(hout + (size_t)b * HH + j, og * ftanh(cn));
#pragma unroll
                    for (int g = 0; g < 4; g++) xv_cur[m][g] = xv_nxt[m][g];
                }
            }
        }

        // ================= layer 1: h1(u-2).W_hh1 + h0(u-1).W_ih1 ========
        if (u >= 1) {
            ull acc1[4][4];
#pragma unroll
            for (int m = 0; m < 4; m++)
#pragma unroll
                for (int g = 0; g < 4; g++) acc1[m][g] = 0ull;

            // ---- preload first 2 ih k-iters (hides L2 latency behind hh GEMM)
            ulonglong2 wb[2][4];
#pragma unroll
            for (int p = 0; p < 2; p++)
#pragma unroll
                for (int g = 0; g < 4; g++)
                    wb[p][g] = __ldg((const ulonglong2*)
                                     (wih_t + (size_t)g * HH * HH + p * 4));

            // ---- hh GEMM (SMEM-resident W_hh1)
#pragma unroll 4
            for (int k = kb; k < kb + 128; k += 4) {
                ulonglong2 h2[4], w2[4];
#pragma unroll
                for (int m = 0; m < 4; m++)
                    h2[m] = *(ulonglong2*)&Hs1[(br + 8 * m) * WPAD + k];
#pragma unroll
                for (int g = 0; g < 4; g++)
                    w2[g] = *(ulonglong2*)&Ws1[(g * 16 + jl) * WPAD + k];
#pragma unroll
                for (int m = 0; m < 4; m++)
#pragma unroll
                    for (int g = 0; g < 4; g++) {
                        ffma2(acc1[m][g], h2[m].x, w2[g].x);
                        ffma2(acc1[m][g], h2[m].y, w2[g].y);
                    }
            }

            // ---- ih GEMM: W_ih1 from L2 via LDG, 2-iteration register pipeline
#pragma unroll
            for (int it = 0; it < 32; it += 2) {
                ulonglong2 cur[2][4];
#pragma unroll
                for (int p = 0; p < 2; p++)
#pragma unroll
                    for (int g = 0; g < 4; g++) cur[p][g] = wb[p][g];
                if (it + 2 < 32) {
#pragma unroll
                    for (int p = 0; p < 2; p++)
#pragma unroll
                        for (int g = 0; g < 4; g++)
                            wb[p][g] = __ldg((const ulonglong2*)
                                (wih_t + (size_t)g * HH * HH + (it + 2 + p) * 4));
                }
#pragma unroll
                for (int p = 0; p < 2; p++) {
                    int k = kb + (it + p) * 4;
                    ulonglong2 h2[4];
#pragma unroll
                    for (int m = 0; m < 4; m++)
                        h2[m] = *(ulonglong2*)&Hs0[(br + 8 * m) * WPAD + k];
#pragma unroll
                    for (int m = 0; m < 4; m++)
#pragma unroll
                        for (int g = 0; g < 4; g++) {
                            ffma2(acc1[m][g], h2[m].x, cur[p][g].x);
                            ffma2(acc1[m][g], h2[m].y, cur[p][g].y);
                        }
                }
            }

            // ---- kg1 publishes layer-1 partials into Rs1
            if (kg == 1) {
#pragma unroll
                for (int m = 0; m < 4; m++)
#pragma unroll
                    for (int g = 0; g < 4; g++)
                        Rs1[(8 * m + br) * RPAD + g * 16 + jl] = red2(acc1[m][g]);
            }
            __syncthreads();

            // ---- kg0: epilogue layer 1 -> h1(u-1)
            if (kg == 0) {
                float* hout = h1buf + (size_t)((u - 1) & 1) * BHH;
#pragma unroll
                for (int m = 0; m < 4; m++) {
                    int b = bb + br + 8 * m;
                    const float* rrow = &Rs1[(8 * m + br) * RPAD];
                    float vi = red2(acc1[m][0]) + rrow[0 * 16 + jl] + bias1[0];
                    float vf = red2(acc1[m][1]) + rrow[1 * 16 + jl] + bias1[1];
                    float vg = red2(acc1[m][2]) + rrow[2 * 16 + jl] + bias1[2];
                    float vo = red2(acc1[m][3]) + rrow[3 * 16 + jl] + bias1[3];

                    float ig = fsig(vi), fg = fsig(vf), gg = ftanh(vg), og = fsig(vo);
                    float cn = fg * cacc1[m] + ig * gg;
                    cacc1[m] = cn;
                    float hn = og * ftanh(cn);
                    __stcg(hout + (size_t)b * HH + j, hn);
                    if (u == TT) hlast[(size_t)b * HH + j] = hn;
                }
            }
        }

        // ---- arrive
        __syncthreads();
        if (tid == 0) {
            __threadfence();
            *(volatile unsigned*)&g_flag[(bt * GROUP_CTAS + jt) * 32] =
                (unsigned)(u + 1);
        }
    }
}

// ---------------- launcher ---------------------------------------------------
extern "C" void kernel_launch(void* const* d_in, const int* in_sizes, int n_in,
                              void* d_out, int out_size)
{
    const float* x     = (const float*)d_in[0];
    const float* W_ih0 = (const float*)d_in[1];
    const float* W_hh0 = (const float*)d_in[2];
    const float* b_ih0 = (const float*)d_in[3];
    const float* b_hh0 = (const float*)d_in[4];
    const float* W_ih1 = (const float*)d_in[5];
    const float* W_hh1 = (const float*)d_in[6];
    const float* b_ih1 = (const float*)d_in[7];
    const float* b_hh1 = (const float*)d_in[8];
    const float* W_fc  = (const float*)d_in[9];
    float* outp = (float*)d_out;
    (void)in_sizes; (void)n_in; (void)out_size;

    float *XP, *H0, *H1, *HLAST;
    cudaGetSymbolAddress((void**)&XP,    g_XP);
    cudaGetSymbolAddress((void**)&H0,    g_H0);
    cudaGetSymbolAddress((void**)&H1,    g_H1);
    cudaGetSymbolAddress((void**)&HLAST, g_HLAST);

    static bool attr_set = false;
    if (!attr_set) {
        cudaFuncSetAttribute(lstm_fused_kernel,
                             cudaFuncAttributeMaxDynamicSharedMemorySize,
                             FUSED_FLOATS * (int)sizeof(float));
        attr_set = true;
    }
    const size_t fsmemB = FUSED_FLOATS * sizeof(float);

    init_kernel<<<(2 * BHH + 255) / 256, 256>>>();
    gemm_bias_kernel<DIN><<<dim3(16, 4, TT), 256>>>(
        x, (size_t)TT * DIN, (size_t)DIN, W_ih0, b_ih0, b_hh0, XP, G4);
    lstm_fused_kernel<<<NB_CTAS, 256, fsmemB>>>(
        XP, W_hh0, W_hh1, W_ih1, b_ih1, b_hh1, H0, H1, HLAST);

    // ---------- final FC: out = h1_last @ W_fc^T ----------
    gemm_bias_kernel<HH><<<dim3(2, 4, 1), 256>>>(
        HLAST, (size_t)HH, 0, W_fc, nullptr, nullptr, outp, OUTF);
}